// round 17
// baseline (speedup 1.0000x reference)
#include <cuda_runtime.h>
#include <cuda_fp16.h>
#include <math.h>
#include <stdint.h>

#define BB 2
#define SQ 2048
#define DD 512
#define NH 8
#define HD 64
#define SCALE 0.125f
#define CBIAS 0.5f
#define LOG2E 1.4426950408889634f
#define SCALE_L2E (SCALE * LOG2E)
#define NKT (SQ / 64)

// Scratch (device globals)
__device__ uint32_t g_xh[BB * SQ * (DD / 2)], g_xl[BB * SQ * (DD / 2)];
__device__ uint32_t g_Wsh[3 * DD * DD / 2], g_Wsl[3 * DD * DD / 2];
__device__ uint32_t g_Woh[DD * DD / 2], g_Wol[DD * DD / 2];
__device__ uint32_t g_Qf[BB * SQ * (DD / 2)];    // Q pre-scaled fp16x2
__device__ uint32_t g_Kf[BB * SQ * (DD / 2)];    // K fp16x2
__device__ uint32_t g_Vf[BB * SQ * (DD / 2)];    // V fp16x2
__device__ uint32_t g_ctxh[BB * SQ * (DD / 2)];  // ctx split bf16
__device__ uint32_t g_ctxl[BB * SQ * (DD / 2)];
__device__ uint32_t g_bias_h[(size_t)BB * SQ * SQ / 2]; // bias*log2e fp16x2

// ---- helpers ----
__device__ __forceinline__ uint32_t pack_bf2(float e0, float e1) {
    uint32_t r; asm("cvt.rn.bf16x2.f32 %0, %1, %2;" : "=r"(r) : "f"(e1), "f"(e0)); return r;
}
__device__ __forceinline__ float bf2_lo_f(uint32_t p) { return __uint_as_float(p << 16); }
__device__ __forceinline__ float bf2_hi_f(uint32_t p) { return __uint_as_float(p & 0xffff0000u); }
__device__ __forceinline__ void split_bf2(float x, float y, uint32_t& hi, uint32_t& lo) {
    hi = pack_bf2(x, y);
    lo = pack_bf2(x - bf2_lo_f(hi), y - bf2_hi_f(hi));
}
__device__ __forceinline__ uint32_t pack_h2(float a, float b) {
    __half2 h = __floats2half2_rn(a, b);
    uint32_t u; memcpy(&u, &h, 4); return u;
}
__device__ __forceinline__ uint32_t ex2_h2(uint32_t x) {
    uint32_t r; asm("ex2.approx.f16x2 %0, %1;" : "=r"(r) : "r"(x)); return r;
}
__device__ __forceinline__ float2 h2f2(uint32_t x) {
    __half2 h; memcpy(&h, &x, 4); return __half22float2(h);
}
__device__ __forceinline__ void mma_bf16(float c[4],
    uint32_t a0, uint32_t a1, uint32_t a2, uint32_t a3, uint32_t b0, uint32_t b1)
{
    asm volatile("mma.sync.aligned.m16n8k16.row.col.f32.bf16.bf16.f32 "
        "{%0,%1,%2,%3}, {%4,%5,%6,%7}, {%8,%9}, {%0,%1,%2,%3};"
        : "+f"(c[0]), "+f"(c[1]), "+f"(c[2]), "+f"(c[3])
        : "r"(a0), "r"(a1), "r"(a2), "r"(a3), "r"(b0), "r"(b1));
}
__device__ __forceinline__ void mma_f16(float c[4],
    uint32_t a0, uint32_t a1, uint32_t a2, uint32_t a3, uint32_t b0, uint32_t b1)
{
    asm volatile("mma.sync.aligned.m16n8k16.row.col.f32.f16.f16.f32 "
        "{%0,%1,%2,%3}, {%4,%5,%6,%7}, {%8,%9}, {%0,%1,%2,%3};"
        : "+f"(c[0]), "+f"(c[1]), "+f"(c[2]), "+f"(c[3])
        : "r"(a0), "r"(a1), "r"(a2), "r"(a3), "r"(b0), "r"(b1));
}
__device__ __forceinline__ void ldsm_x4(uint32_t& r0, uint32_t& r1,
                                        uint32_t& r2, uint32_t& r3, uint32_t addr)
{
    asm volatile("ldmatrix.sync.aligned.m8n8.x4.shared.b16 {%0,%1,%2,%3}, [%4];"
        : "=r"(r0), "=r"(r1), "=r"(r2), "=r"(r3) : "r"(addr));
}
__device__ __forceinline__ void ldsm_x4t(uint32_t& r0, uint32_t& r1,
                                         uint32_t& r2, uint32_t& r3, uint32_t addr)
{
    asm volatile("ldmatrix.sync.aligned.m8n8.x4.trans.shared.b16 {%0,%1,%2,%3}, [%4];"
        : "=r"(r0), "=r"(r1), "=r"(r2), "=r"(r3) : "r"(addr));
}
__device__ __forceinline__ uint32_t smaddr(const void* p) {
    return (uint32_t)__cvta_generic_to_shared(p);
}
#define CP16(dst, src) asm volatile("cp.async.cg.shared.global [%0], [%1], 16;" :: "r"(dst), "l"(src))
#define CPCOMMIT()     asm volatile("cp.async.commit_group;")
#define CPWAIT(n)      asm volatile("cp.async.wait_group %0;" :: "n"(n))

// ---------------------------------------------------------------------------
// Prep: split x + Wq/Wk/Wv/Wo into bf16 hi/lo word arrays (~25 MB traffic).
// ---------------------------------------------------------------------------
__global__ __launch_bounds__(256) void prep_kernel(
    const float* __restrict__ x,
    const float* __restrict__ Wq, const float* __restrict__ Wk,
    const float* __restrict__ Wv, const float* __restrict__ Wo)
{
    const int NX2 = (BB * SQ * DD) / 2;      // 1048576
    const int NW2 = (DD * DD) / 2;           // 131072
    const int ntot = NX2 + 4 * NW2;
    const int nthreads = gridDim.x * 256;
    for (int p = blockIdx.x * 256 + threadIdx.x; p < ntot; p += nthreads) {
        const float* src; uint32_t* dh; uint32_t* dl; int off;
        if (p < NX2)                 { src = x;  dh = g_xh;  dl = g_xl;  off = p; }
        else if (p < NX2 + NW2)      { src = Wq; dh = g_Wsh; dl = g_Wsl; off = p - NX2; }
        else if (p < NX2 + 2 * NW2)  { src = Wk; dh = g_Wsh + NW2; dl = g_Wsl + NW2; off = p - NX2 - NW2; }
        else if (p < NX2 + 3 * NW2)  { src = Wv; dh = g_Wsh + 2 * NW2; dl = g_Wsl + 2 * NW2; off = p - NX2 - 2 * NW2; }
        else                         { src = Wo; dh = g_Woh; dl = g_Wol; off = p - NX2 - 3 * NW2; }
        float2 v = ((const float2*)src)[off];
        split_bf2(v.x, v.y, dh[off], dl[off]);
    }
}

// ---------------------------------------------------------------------------
// Streaming split-operand bf16x3 GEMM, 3-stage cp.async pipeline.
// MODE: 0 = fp32 out, 1 = K fp16, 2 = V fp16, 3 = Q scaled fp16.
// ---------------------------------------------------------------------------
#define GP3 20
#define SGA (128 * GP3)
#define SGW (64 * GP3)
#define SG3 (2 * SGA + 2 * SGW)          // 7680 words / stage
#define GEMM_SMEM3 (3 * SG3 * 4)         // 92160 B

template <int MODE>
__device__ __forceinline__ void gemm_stream_body(
    const uint32_t* __restrict__ Ah, const uint32_t* __restrict__ Al,
    const uint32_t* __restrict__ Wh, const uint32_t* __restrict__ Wl,
    const float* __restrict__ bias, float* __restrict__ outp,
    int m0, int n0)
{
    extern __shared__ uint32_t smu[];
    const int tid = threadIdx.x;
    const int w = tid >> 5, lane = tid & 31;
    const int g = lane >> 2, t = lane & 3;
    const int lm_m = lane >> 3, lm_r = lane & 7;

    float acc[8][4] = {};

    auto issue = [&](int s, int k0w) {
        uint32_t* ah = smu + s * SG3;
        uint32_t* al = ah + SGA;
        uint32_t* wh = al + SGA;
        uint32_t* wl = wh + SGW;
        #pragma unroll
        for (int i = 0; i < 2; i++) {
            int e = tid + i * 256;
            int r = e >> 2, c4 = (e & 3) * 4;
            CP16(smaddr(ah + r * GP3 + c4), Ah + (size_t)(m0 + r) * (DD/2) + k0w + c4);
            CP16(smaddr(al + r * GP3 + c4), Al + (size_t)(m0 + r) * (DD/2) + k0w + c4);
        }
        {
            int r = tid >> 2, c4 = (tid & 3) * 4;
            CP16(smaddr(wh + r * GP3 + c4), Wh + (size_t)(n0 + r) * (DD/2) + k0w + c4);
            CP16(smaddr(wl + r * GP3 + c4), Wl + (size_t)(n0 + r) * (DD/2) + k0w + c4);
        }
        CPCOMMIT();
    };

    issue(0, 0);
    issue(1, 16);

    for (int it = 0; it < 16; it++) {
        if (it < 14) { CPWAIT(1); } else { CPWAIT(0); }
        __syncthreads();
        if (it + 2 < 16) issue((it + 2) % 3, (it + 2) * 16);

        uint32_t* ah_s = smu + (it % 3) * SG3;
        uint32_t* al_s = ah_s + SGA;
        uint32_t* wh_s = al_s + SGA;
        uint32_t* wl_s = wh_s + SGW;

        #pragma unroll
        for (int kk = 0; kk < 2; kk++) {
            uint32_t ah0, ah1, ah2, ah3, al0, al1, al2, al3;
            {
                int ar = w * 16 + (lm_m & 1) * 8 + lm_r;
                int ac = kk * 8 + (lm_m >> 1) * 4;
                ldsm_x4(ah0, ah1, ah2, ah3, smaddr(ah_s + ar * GP3 + ac));
                ldsm_x4(al0, al1, al2, al3, smaddr(al_s + ar * GP3 + ac));
            }
            #pragma unroll
            for (int np = 0; np < 4; np++) {
                int br = (2 * np + (lm_m >> 1)) * 8 + lm_r;
                int bc = kk * 8 + (lm_m & 1) * 4;
                uint32_t bh0, bh1, bh2, bh3, bl0, bl1, bl2, bl3;
                ldsm_x4(bh0, bh1, bh2, bh3, smaddr(wh_s + br * GP3 + bc));
                ldsm_x4(bl0, bl1, bl2, bl3, smaddr(wl_s + br * GP3 + bc));
                mma_bf16(acc[2*np],   ah0, ah1, ah2, ah3, bh0, bh1);
                mma_bf16(acc[2*np],   ah0, ah1, ah2, ah3, bl0, bl1);
                mma_bf16(acc[2*np],   al0, al1, al2, al3, bh0, bh1);
                mma_bf16(acc[2*np+1], ah0, ah1, ah2, ah3, bh2, bh3);
                mma_bf16(acc[2*np+1], ah0, ah1, ah2, ah3, bl2, bl3);
                mma_bf16(acc[2*np+1], al0, al1, al2, al3, bh2, bh3);
            }
        }
    }

    #pragma unroll
    for (int ns = 0; ns < 8; ns++) {
        int n = n0 + ns * 8 + 2 * t;
        float b0 = bias[n], b1 = bias[n + 1];
        int r = m0 + w * 16 + g;
        float v00 = acc[ns][0] + b0, v01 = acc[ns][1] + b1;
        float v10 = acc[ns][2] + b0, v11 = acc[ns][3] + b1;
        size_t wcol = (size_t)(n >> 1);
        if (MODE == 0) {
            *(float2*)&outp[(size_t)r * DD + n] = make_float2(v00, v01);
            *(float2*)&outp[(size_t)(r + 8) * DD + n] = make_float2(v10, v11);
        } else if (MODE == 1) {
            g_Kf[(size_t)r * (DD/2) + wcol]     = pack_h2(v00, v01);
            g_Kf[(size_t)(r+8) * (DD/2) + wcol] = pack_h2(v10, v11);
        } else if (MODE == 2) {
            g_Vf[(size_t)r * (DD/2) + wcol]     = pack_h2(v00, v01);
            g_Vf[(size_t)(r+8) * (DD/2) + wcol] = pack_h2(v10, v11);
        } else {
            g_Qf[(size_t)r * (DD/2) + wcol]     = pack_h2(v00 * SCALE_L2E, v01 * SCALE_L2E);
            g_Qf[(size_t)(r+8) * (DD/2) + wcol] = pack_h2(v10 * SCALE_L2E, v11 * SCALE_L2E);
        }
    }
}

// ---------------------------------------------------------------------------
// Fused QKV (streaming) + bias plane.
// ---------------------------------------------------------------------------
__global__ __launch_bounds__(256, 2) void qkv_bias_kernel(
    const float* __restrict__ bq, const float* __restrict__ bk,
    const float* __restrict__ bv,
    const float* __restrict__ ipa, const float* __restrict__ assoc,
    const float* __restrict__ amask,
    const int* __restrict__ cid, const unsigned char* __restrict__ kpm)
{
    const int NW2 = (DD * DD) / 2;
    int m0 = blockIdx.y * 128, n0 = blockIdx.x * 64;
    if (blockIdx.z == 0)
        gemm_stream_body<3>(g_xh, g_xl, g_Wsh, g_Wsl, bq, nullptr, m0, n0);
    else if (blockIdx.z == 1)
        gemm_stream_body<1>(g_xh, g_xl, g_Wsh + NW2, g_Wsl + NW2, bk, nullptr, m0, n0);
    else if (blockIdx.z == 2)
        gemm_stream_body<2>(g_xh, g_xl, g_Wsh + 2 * NW2, g_Wsl + 2 * NW2, bv, nullptr, m0, n0);
    else {
        const int nthreads = gridDim.x * gridDim.y * 256;
        const int tglob = (blockIdx.y * gridDim.x + blockIdx.x) * 256 + threadIdx.x;
        const int npacks = (BB * SQ * SQ) / 4;
        for (int p = tglob; p < npacks; p += nthreads) {
            int idx = p * 4;
            int k4 = idx & (SQ - 1);
            int t2 = idx >> 11;
            int q = t2 & (SQ - 1);
            int b = t2 >> 11;
            float4 vi = *(const float4*)&ipa[idx];
            float4 va = *(const float4*)&assoc[idx];
            float4 vm = *(const float4*)&amask[q * SQ + k4];
            int4 ck4 = *(const int4*)&cid[b * SQ + k4];
            uchar4 kp4 = *(const uchar4*)&kpm[b * SQ + k4];
            int cq = cid[b * SQ + q];
            bool qv = cq >= 0;
            float r0 = (vi.x + va.x + vm.x) * LOG2E;
            float r1 = (vi.y + va.y + vm.y) * LOG2E;
            float r2 = (vi.z + va.z + vm.z) * LOG2E;
            float r3 = (vi.w + va.w + vm.w) * LOG2E;
            const float cb = CBIAS * LOG2E;
            if (qv && cq == ck4.x && q != k4)     r0 += cb;
            if (qv && cq == ck4.y && q != k4 + 1) r1 += cb;
            if (qv && cq == ck4.z && q != k4 + 2) r2 += cb;
            if (qv && cq == ck4.w && q != k4 + 3) r3 += cb;
            if (kp4.x) r0 = -60000.0f;
            if (kp4.y) r1 = -60000.0f;
            if (kp4.z) r2 = -60000.0f;
            if (kp4.w) r3 = -60000.0f;
            g_bias_h[(size_t)p * 2]     = pack_h2(r0, r1);
            g_bias_h[(size_t)p * 2 + 1] = pack_h2(r2, r3);
        }
    }
}

__global__ __launch_bounds__(256, 2) void proj_tc_kernel(
    const float* __restrict__ bo, float* __restrict__ out)
{
    gemm_stream_body<0>(g_ctxh, g_ctxl, g_Woh, g_Wol, bo, out,
                        blockIdx.y * 128, blockIdx.x * 64);
}

// ---------------------------------------------------------------------------
// fp16 flash attention (unchanged from R16)
// ---------------------------------------------------------------------------
#define KP3 36
#define KST (64 * KP3)
#define VST (64 * KP3)
#define PST (128 * KP3)
#define ATTN_SMEM ((2 * KST + 2 * VST + PST) * 4)

__global__ __launch_bounds__(256, 2) void attn_tc_kernel()
{
    extern __shared__ uint32_t smu[];
    uint32_t* Kst = smu;
    uint32_t* Vst = Kst + 2 * KST;
    uint32_t* Pst = Vst + 2 * VST;

    const int tid = threadIdx.x;
    const int w = tid >> 5, lane = tid & 31;
    const int g = lane >> 2, t = lane & 3;
    const int lm_m = lane >> 3, lm_r = lane & 7;
    const int q0 = blockIdx.x * 128;
    const int h  = blockIdx.y;
    const int b  = blockIdx.z;

    const uint32_t* Ksrc = g_Kf + (size_t)b * SQ * (DD/2) + h * (HD/2);
    const uint32_t* Vsrc = g_Vf + (size_t)b * SQ * (DD/2) + h * (HD/2);

    #pragma unroll
    for (int i = 0; i < 2; i++) {
        int e = tid + i * 256;
        int r = e >> 3, c4 = (e & 7) * 4;
        CP16(smaddr(Kst + r * KP3 + c4), Ksrc + (size_t)r * (DD/2) + c4);
        CP16(smaddr(Vst + r * KP3 + c4), Vsrc + (size_t)r * (DD/2) + c4);
    }
    CPCOMMIT();

    const uint32_t* Qp = g_Qf + (size_t)(b * SQ + q0) * (DD/2) + h * (HD/2);
    uint32_t qf[4][4];
    #pragma unroll
    for (int kk = 0; kk < 4; kk++) {
        #pragma unroll
        for (int i = 0; i < 4; i++) {
            int r = w * 16 + g + (i & 1) * 8;
            int wc = kk * 8 + t + (i >> 1) * 4;
            qf[kk][i] = Qp[(size_t)r * (DD/2) + wc];
        }
    }

    float mrow[2] = { -1e30f, -1e30f };
    float lrow[2] = { 0.0f, 0.0f };
    float o[8][4] = {};
    const uint32_t* Bgh = g_bias_h + (size_t)(b * SQ + q0) * (SQ / 2);

    for (int kt = 0; kt < NKT; kt++) {
        CPWAIT(0);
        __syncthreads();

        if (kt + 1 < NKT) {
            int s = (kt + 1) & 1;
            int k0n = (kt + 1) * 64;
            #pragma unroll
            for (int i = 0; i < 2; i++) {
                int e = tid + i * 256;
                int r = e >> 3, c4 = (e & 7) * 4;
                CP16(smaddr(Kst + s * KST + r * KP3 + c4),
                     Ksrc + (size_t)(k0n + r) * (DD/2) + c4);
                CP16(smaddr(Vst + s * VST + r * KP3 + c4),
                     Vsrc + (size_t)(k0n + r) * (DD/2) + c4);
            }
            CPCOMMIT();
        }

        const uint32_t* Ks = Kst + (kt & 1) * KST;
        const uint32_t* Vs = Vst + (kt & 1) * VST;
        const int k0 = kt * 64;

        uint32_t bw0[8], bw1[8];
        #pragma unroll
        for (int ns = 0; ns < 8; ns++) {
            int wcol = (k0 + ns * 8) / 2 + t;
            bw0[ns] = Bgh[(size_t)(w * 16 + g) * (SQ / 2) + wcol];
            bw1[ns] = Bgh[(size_t)(w * 16 + g + 8) * (SQ / 2) + wcol];
        }

        float s[8][4] = {};
        #pragma unroll
        for (int kk = 0; kk < 4; kk++) {
            #pragma unroll
            for (int np = 0; np < 4; np++) {
                int br = (2 * np + (lm_m >> 1)) * 8 + lm_r;
                int bc = kk * 8 + (lm_m & 1) * 4;
                uint32_t b0a, b1a, b0b, b1b;
                ldsm_x4(b0a, b1a, b0b, b1b, smaddr(Ks + br * KP3 + bc));
                mma_f16(s[2*np],   qf[kk][0], qf[kk][1], qf[kk][2], qf[kk][3], b0a, b1a);
                mma_f16(s[2*np+1], qf[kk][0], qf[kk][1], qf[kk][2], qf[kk][3], b0b, b1b);
            }
        }

        #pragma unroll
        for (int ns = 0; ns < 8; ns++) {
            float2 b0v = h2f2(bw0[ns]);
            float2 b1v = h2f2(bw1[ns]);
            s[ns][0] += b0v.x; s[ns][1] += b0v.y;
            s[ns][2] += b1v.x; s[ns][3] += b1v.y;
        }

        float tm0 = -1e30f, tm1 = -1e30f;
        #pragma unroll
        for (int ns = 0; ns < 8; ns++) {
            tm0 = fmaxf(tm0, fmaxf(s[ns][0], s[ns][1]));
            tm1 = fmaxf(tm1, fmaxf(s[ns][2], s[ns][3]));
        }
        tm0 = fmaxf(tm0, __shfl_xor_sync(0xffffffffu, tm0, 1));
        tm0 = fmaxf(tm0, __shfl_xor_sync(0xffffffffu, tm0, 2));
        tm1 = fmaxf(tm1, __shfl_xor_sync(0xffffffffu, tm1, 1));
        tm1 = fmaxf(tm1, __shfl_xor_sync(0xffffffffu, tm1, 2));

        float mn0 = fmaxf(mrow[0], tm0), mn1 = fmaxf(mrow[1], tm1);
        float cr0 = exp2f(mrow[0] - mn0), cr1 = exp2f(mrow[1] - mn1);
        float sum0 = 0.0f, sum1 = 0.0f;
        const int prow = w * 16 + g;
        #pragma unroll
        for (int ns = 0; ns < 8; ns++) {
            uint32_t pa = ex2_h2(pack_h2(s[ns][0] - mn0, s[ns][1] - mn0));
            uint32_t pb = ex2_h2(pack_h2(s[ns][2] - mn1, s[ns][3] - mn1));
            Pst[prow * KP3 + ns * 4 + t]       = pa;
            Pst[(prow + 8) * KP3 + ns * 4 + t] = pb;
            float2 ua = h2f2(pa), ub = h2f2(pb);
            sum0 += ua.x + ua.y;
            sum1 += ub.x + ub.y;
            o[ns][0] *= cr0; o[ns][1] *= cr0;
            o[ns][2] *= cr1; o[ns][3] *= cr1;
        }
        sum0 += __shfl_xor_sync(0xffffffffu, sum0, 1);
        sum0 += __shfl_xor_sync(0xffffffffu, sum0, 2);
        sum1 += __shfl_xor_sync(0xffffffffu, sum1, 1);
        sum1 += __shfl_xor_sync(0xffffffffu, sum1, 2);
        lrow[0] = lrow[0] * cr0 + sum0;
        lrow[1] = lrow[1] * cr1 + sum1;
        mrow[0] = mn0; mrow[1] = mn1;
        __syncwarp();

        #pragma unroll
        for (int kk = 0; kk < 4; kk++) {
            uint32_t a0, a1, a2, a3;
            {
                int ar = w * 16 + (lm_m & 1) * 8 + lm_r;
                int ac = kk * 8 + (lm_m >> 1) * 4;
                ldsm_x4(a0, a1, a2, a3, smaddr(Pst + ar * KP3 + ac));
            }
            #pragma unroll
            for (int np = 0; np < 4; np++) {
                int krow = kk * 16 + (lane & 15);
                int colw = np * 8 + ((lane >> 4) & 1) * 4;
                uint32_t v0, v1, v2, v3;
                ldsm_x4t(v0, v1, v2, v3, smaddr(Vs + krow * KP3 + colw));
                mma_f16(o[2*np],   a0, a1, a2, a3, v0, v1);
                mma_f16(o[2*np+1], a0, a1, a2, a3, v2, v3);
            }
        }
    }

    float inv0 = 1.0f / lrow[0], inv1 = 1.0f / lrow[1];
    uint32_t* Ch = g_ctxh + (size_t)(b * SQ + q0) * (DD/2) + h * (HD/2);
    uint32_t* Cl = g_ctxl + (size_t)(b * SQ + q0) * (DD/2) + h * (HD/2);
    #pragma unroll
    for (int ns = 0; ns < 8; ns++) {
        int wc = ns * 4 + t;
        uint32_t hi0, lo0, hi1, lo1;
        split_bf2(o[ns][0] * inv0, o[ns][1] * inv0, hi0, lo0);
        split_bf2(o[ns][2] * inv1, o[ns][3] * inv1, hi1, lo1);
        Ch[(size_t)(w * 16 + g) * (DD/2) + wc] = hi0;
        Cl[(size_t)(w * 16 + g) * (DD/2) + wc] = lo0;
        Ch[(size_t)(w * 16 + g + 8) * (DD/2) + wc] = hi1;
        Cl[(size_t)(w * 16 + g + 8) * (DD/2) + wc] = lo1;
    }
}

// ---------------------------------------------------------------------------
extern "C" void kernel_launch(void* const* d_in, const int* in_sizes, int n_in,
                              void* d_out, int out_size)
{
    const float* x     = (const float*)d_in[0];
    const float* Wq    = (const float*)d_in[1];
    const float* bq    = (const float*)d_in[2];
    const float* Wk    = (const float*)d_in[3];
    const float* bk    = (const float*)d_in[4];
    const float* Wv    = (const float*)d_in[5];
    const float* bv    = (const float*)d_in[6];
    const float* Wo    = (const float*)d_in[7];
    const float* bo    = (const float*)d_in[8];
    const float* amask = (const float*)d_in[9];
    const float* ipa   = (const float*)d_in[10];
    const float* assoc = (const float*)d_in[11];
    const int* cid            = (const int*)d_in[12];
    const unsigned char* kpm  = (const unsigned char*)d_in[13];
    float* out = (float*)d_out;

    cudaFuncSetAttribute(attn_tc_kernel, cudaFuncAttributeMaxDynamicSharedMemorySize, ATTN_SMEM);
    cudaFuncSetAttribute(qkv_bias_kernel, cudaFuncAttributeMaxDynamicSharedMemorySize, GEMM_SMEM3);
    cudaFuncSetAttribute(proj_tc_kernel, cudaFuncAttributeMaxDynamicSharedMemorySize, GEMM_SMEM3);

    // Split x + weights (small, ~25 MB traffic)
    prep_kernel<<<256, 256>>>(x, Wq, Wk, Wv, Wo);

    // Streaming QKV + fp16 bias plane
    qkv_bias_kernel<<<dim3(DD / 64, (BB * SQ) / 128, 4), 256, GEMM_SMEM3>>>(
        bq, bk, bv, ipa, assoc, amask, cid, kpm);

    // fp16 flash attention
    attn_tc_kernel<<<dim3(SQ / 128, NH, BB), 256, ATTN_SMEM>>>();

    // Streaming output projection
    proj_tc_kernel<<<dim3(DD / 64, (BB * SQ) / 128), 256, GEMM_SMEM3>>>(bo, out);
}